// round 13
// baseline (speedup 1.0000x reference)
#include <cuda_runtime.h>
#include <math.h>

#define BB 16
#define HH 512
#define WW 512
#define NTOT (BB * HH * WW)

#define RAD 10
#define TILE_H 32
#define TILE_W 64
#define SROWS (TILE_H + 2 * RAD)  // 52
#define GX (WW / TILE_W)          // 8
#define GYT (HH / TILE_H)         // 16
#define NBB 1024                  // K2b blocks (= partial slots)

// Scratch (no allocation allowed in kernel_launch)
__device__ unsigned g_mask[BB * HH * 16];   // fg bitmask, 16 u32 words/row
__device__ unsigned char g_d8[NTOT];        // per-px dmin (0..100), u8
__device__ float g_pl[NBB];
__device__ float g_pf[NBB];
__device__ unsigned g_done = 0;  // last-block counter (self-resetting)

// ---------------------------------------------------------------------------
// K1: build fg bitmask. Pure streaming: each thread loads 4 independent
// float4s (16 cols), builds 16 bits locally, stores one u16. MLP=4/thread.
// ---------------------------------------------------------------------------
__global__ __launch_bounds__(256) void k1_mask(const float* __restrict__ tgt) {
    const int gid = blockIdx.x * 256 + threadIdx.x;
    const int row = gid >> 5;
    const int c16 = gid & 31;
    const float4* p = (const float4*)(tgt + (size_t)row * WW + c16 * 16);
    float4 v0 = p[0], v1 = p[1], v2 = p[2], v3 = p[3];
    unsigned m = 0;
    m |= (v0.x > 0.5f) ? 1u << 0 : 0u;
    m |= (v0.y > 0.5f) ? 1u << 1 : 0u;
    m |= (v0.z > 0.5f) ? 1u << 2 : 0u;
    m |= (v0.w > 0.5f) ? 1u << 3 : 0u;
    m |= (v1.x > 0.5f) ? 1u << 4 : 0u;
    m |= (v1.y > 0.5f) ? 1u << 5 : 0u;
    m |= (v1.z > 0.5f) ? 1u << 6 : 0u;
    m |= (v1.w > 0.5f) ? 1u << 7 : 0u;
    m |= (v2.x > 0.5f) ? 1u << 8 : 0u;
    m |= (v2.y > 0.5f) ? 1u << 9 : 0u;
    m |= (v2.z > 0.5f) ? 1u << 10 : 0u;
    m |= (v2.w > 0.5f) ? 1u << 11 : 0u;
    m |= (v3.x > 0.5f) ? 1u << 12 : 0u;
    m |= (v3.y > 0.5f) ? 1u << 13 : 0u;
    m |= (v3.z > 0.5f) ? 1u << 14 : 0u;
    m |= (v3.w > 0.5f) ? 1u << 15 : 0u;
    ((unsigned short*)g_mask)[(size_t)row * 32 + c16] = (unsigned short)m;
}

// ---------------------------------------------------------------------------
// K2a: stencil only — per 32x64 tile, compute per-px dmin (clamped 100) and
// store as u8. Pure integer math, no inp, no reduction.
//  1) stage 52x4 mask words (single pass, tid<208)
//  2) warp row-activity via one ballot; sparse tap loop (~2 avg). Per tap:
//     f^2 for the lane's 2 cols from mask bits (funnelshift+clz/ffs, clamp
//     10); min-plus with w=min(dm^2,100) — clamp neutralizes out-of-window
//     taps and ties with the sentinel 100. All exact ints.
//  3) store 4 u16 (2 packed dmins each), 64B/row/warp coalesced.
// dmin=100 where no fg within dist 10 -> heatmap ~0 (loss-equiv, < 1e-5).
// ---------------------------------------------------------------------------
__global__ __launch_bounds__(256) void k2a_dmin() {
    const int tid = threadIdx.x;
    const int tx = tid & 31;  // cols 2tx, 2tx+1
    const int ty = tid >> 5;  // rows ty*4 .. ty*4+3
    const int j0 = blockIdx.x * TILE_W;
    const int i0 = blockIdx.y * TILE_H;
    const int b = blockIdx.z;
    const int r0 = ty * 4;

    __shared__ __align__(16) unsigned smask[SROWS][4];  // 832 B

    // --- 1) stage mask words ---
    const int q = j0 >> 5;
    const unsigned* mb = g_mask + (size_t)b * HH * 16;
    if (tid < SROWS * 4) {
        int rr = tid >> 2;
        int wi = tid & 3;
        int gr = i0 - RAD + rr;
        int gw = q - 1 + wi;
        unsigned v = 0;
        if ((unsigned)gr < HH && (unsigned)gw < 16u) v = mb[gr * 16 + gw];
        smask[rr][wi] = v;
    }
    __syncthreads();

    // --- 2) activity ballot + sparse integer tap loop ---
    unsigned act = 0;
    if (tx < 24) {
        uint4 mw = *(const uint4*)&smask[r0 + tx][0];
        unsigned a = (mw.x & 0xFFC00000u) | mw.y | mw.z | (mw.w & 0x3FFu);
        act = (a != 0u) ? 1u : 0u;
    }
    unsigned rm = __ballot_sync(0xffffffffu, act) & 0xFFFFFFu;

    int acc0[4], acc1[4];
#pragma unroll
    for (int mm = 0; mm < 4; mm++) {
        acc0[mm] = 100;
        acc1[mm] = 100;
    }

    while (rm) {
        int t = __ffs(rm) - 1;
        rm &= rm - 1;
        uint4 mw = *(const uint4*)&smask[r0 + t][0];
        int f2v[2];
#pragma unroll
        for (int u = 0; u < 2; u++) {
            int c = 2 * tx + u;  // tile col; global bit = c + 32
            int bs = c + 22;     // window start bit (col c-10)
            int k = bs >> 5;
            int sh = bs & 31;
            unsigned lo = (k == 0) ? mw.x : ((k == 1) ? mw.y : mw.z);
            unsigned hi = (k == 0) ? mw.y : ((k == 1) ? mw.z : mw.w);
            unsigned win = __funnelshift_r(lo, hi, sh) & 0x1FFFFFu;  // c-10..c+10
            unsigned wl = win & 0x7FFu;          // c-10..c (bit10 = center)
            int dl = __clz(wl) - 21;             // 0..11
            unsigned wr = (win >> 10) | 0x800u;  // c..c+10 + sentinel
            int dr = __ffs((int)wr) - 1;         // 0..11
            int f = min(min(dl, dr), 10);
            f2v[u] = f * f;
        }
        int tm10 = t - 10;
#pragma unroll
        for (int mm = 0; mm < 4; mm++) {
            int dm = tm10 - mm;
            int w = min(dm * dm, 100);  // clamps invalid taps too
            acc0[mm] = min(acc0[mm], f2v[0] + w);
            acc1[mm] = min(acc1[mm], f2v[1] + w);
        }
    }

    // --- 3) store packed u8 pairs ---
    unsigned char* dp = g_d8 + ((size_t)(b * HH + i0 + r0)) * WW + j0 + 2 * tx;
#pragma unroll
    for (int mm = 0; mm < 4; mm++) {
        unsigned short v = (unsigned short)(acc0[mm] | (acc1[mm] << 8));
        *(unsigned short*)(dp + (size_t)mm * WW) = v;
    }
}

// ---------------------------------------------------------------------------
// K2b: pure streamer. 16 consecutive px per thread: 1 uint4 of dmins (u8) +
// 4 float4 of inp, MLP=5 front-batched, no tile structure, no barriers
// (except LUT init). Branch-free select epilogue:
//   pos = (d==0) <=> fg px (exact); h = slut[d] (d=100 dominant -> broadcast)
//   a=pos?0.85:0.15; s=pos?q:p; e=pos?q:(p-h); focal=a*s^2; loss=focal*e^2
// Shuffle reduce -> partials; last block folds the final scalar.
// ---------------------------------------------------------------------------
__global__ __launch_bounds__(256) void k2b_loss(const float* __restrict__ inp,
                                                float* __restrict__ out) {
    const int tid = threadIdx.x;
    __shared__ float slut[104];
    __shared__ float swF[8];
    __shared__ float swL[8];
    __shared__ int slast;
    __shared__ double sred[512];

    for (int i = tid; i < 101; i += 256) slut[i] = __expf((float)i * -0.125f);
    __syncthreads();

    const size_t base = ((size_t)blockIdx.x * 256 + tid) * 16;
    uint4 d4 = *(const uint4*)(g_d8 + base);
    const float4* xp = (const float4*)(inp + base);
    float4 xa = xp[0], xb = xp[1], xc = xp[2], xd = xp[3];

    float fsum = 0.0f, lsum = 0.0f;
#define PXE(word, sh, xv)                                     \
    {                                                         \
        int d = ((word) >> (sh)) & 255;                       \
        float h = slut[d];                                    \
        bool pos = (d == 0);                                  \
        float p = __fdividef(1.0f, 1.0f + __expf(-(xv)));     \
        float qq = 1.0f - p;                                  \
        float a = pos ? 0.85f : 0.15f;                        \
        float s = pos ? qq : p;                               \
        float e = pos ? qq : (p - h);                         \
        float f = a * s * s;                                  \
        fsum += f;                                            \
        lsum = fmaf(f * e, e, lsum);                          \
    }
    PXE(d4.x, 0, xa.x) PXE(d4.x, 8, xa.y) PXE(d4.x, 16, xa.z) PXE(d4.x, 24, xa.w)
    PXE(d4.y, 0, xb.x) PXE(d4.y, 8, xb.y) PXE(d4.y, 16, xb.z) PXE(d4.y, 24, xb.w)
    PXE(d4.z, 0, xc.x) PXE(d4.z, 8, xc.y) PXE(d4.z, 16, xc.z) PXE(d4.z, 24, xc.w)
    PXE(d4.w, 0, xd.x) PXE(d4.w, 8, xd.y) PXE(d4.w, 16, xd.z) PXE(d4.w, 24, xd.w)
#undef PXE

    // shuffle reduction (fixed order -> deterministic)
    float thF = fsum, thL = lsum;
#pragma unroll
    for (int off = 16; off > 0; off >>= 1) {
        thF += __shfl_xor_sync(0xffffffffu, thF, off);
        thL += __shfl_xor_sync(0xffffffffu, thL, off);
    }
    if ((tid & 31) == 0) {
        swF[tid >> 5] = thF;
        swL[tid >> 5] = thL;
    }
    __syncthreads();

    if (tid == 0) {
        float F = 0.0f, Lv = 0.0f;
#pragma unroll
        for (int w = 0; w < 8; w++) {
            F += swF[w];
            Lv += swL[w];
        }
        g_pf[blockIdx.x] = F;
        g_pl[blockIdx.x] = Lv;
        __threadfence();
        unsigned old = atomicAdd(&g_done, 1u);
        slast = (old == NBB - 1) ? 1 : 0;
    }
    __syncthreads();

    // last block: fold final scalar
    if (slast) {
        __threadfence();
        double* sFd = sred;
        double* sLd = sred + 256;
        double f = 0.0, l = 0.0;
        for (int i = tid; i < NBB; i += 256) {
            f += (double)g_pf[i];
            l += (double)g_pl[i];
        }
        sFd[tid] = f;
        sLd[tid] = l;
        __syncthreads();
#pragma unroll
        for (int s = 128; s > 0; s >>= 1) {
            if (tid < s) {
                sFd[tid] += sFd[tid + s];
                sLd[tid] += sLd[tid + s];
            }
            __syncthreads();
        }
        if (tid == 0) {
            double n = (double)NTOT;
            double denom = sFd[0] / n + 0.01;
            out[0] = (float)(2.0 * (sLd[0] / n) / denom);
            g_done = 0;  // reset for next graph replay
        }
    }
}

extern "C" void kernel_launch(void* const* d_in, const int* in_sizes, int n_in,
                              void* d_out, int out_size) {
    const float* inp = (const float*)d_in[0];
    const float* tgt = (const float*)d_in[1];
    float* out = (float*)d_out;

    k1_mask<<<(BB * HH * 32) / 256, 256>>>(tgt);
    dim3 g2(GX, GYT, BB);
    k2a_dmin<<<g2, 256>>>();
    k2b_loss<<<NBB, 256>>>(inp, out);
}